// round 17
// baseline (speedup 1.0000x reference)
#include <cuda_runtime.h>
#include <stdint.h>

#define NN 16384
#define BB 64
#define TS 32768          // hash table slots (2x N, power of 2)
#define PREB 64           // blocks in pre kernel
#define POSTB 64          // blocks doing post phases
#define K1B (NN / 8)      // 2048 heavy chunks (8 rows each)
#define MAINB 740         // persistent blocks = 148 SMs x 5 (co-resident, guaranteed)

// ---------------- device scratch (static, no allocation) ----------------
__device__ __align__(16) unsigned int g_Kc[NN];    // per-column hash multiplier = f(x[j])
__device__ unsigned long long g_key[NN];           // per-node signature key hk (0 = isolated)
__device__ __align__(16) unsigned long long g_tab[TS]; // fused slot: key_hi50 | min node idx (0=empty)
__device__ int                g_rank[NN];          // in-block inclusive prefix of is_first
__device__ int                g_bsum[POSTB];       // per-post-block is_first totals
__device__ __align__(16) int  g_counts[BB * NN];   // per-graph color histogram (4 MB)
__device__ __align__(16) int  g_norm2[BB];         // per-graph sum of count^2 (exact int)
__device__ int                g_x64, g_b64;        // dtype flags: 1 if input is int64
__device__ int                g_chunkCtr;          // dynamic ticket for heavy chunks
__device__ unsigned int       g_barCnt[8];         // grid-barrier arrive counters
__device__ unsigned int       g_barGen[8];         // grid-barrier generations (monotonic)

__device__ __forceinline__ unsigned long long mix64(unsigned long long v) {
    v ^= v >> 33; v *= 0xFF51AFD7ED558CCDULL;
    v ^= v >> 33; v *= 0xC4CEB9FE1A85EC53ULL;
    v ^= v >> 33; return v;
}

__device__ __forceinline__ int load_small(const unsigned int* w, int i, int is64) {
    return (int)(is64 ? w[2 * i] : w[i]);
}

// Software grid barrier (sense via monotonic generation; replay-safe).
__device__ __forceinline__ void gridBarrier(int id, unsigned int nblocks) {
    __syncthreads();
    if (threadIdx.x == 0) {
        __threadfence();
        unsigned int gen = atomicAdd(&g_barGen[id], 0u);
        if (atomicAdd(&g_barCnt[id], 1u) == nblocks - 1u) {
            g_barCnt[id] = 0u;
            __threadfence();
            atomicAdd(&g_barGen[id], 1u);           // release
        } else {
            while (atomicAdd(&g_barGen[id], 0u) == gen) { }
        }
        __threadfence();
    }
    __syncthreads();
}

// ---------------- k_pre: dtype detect + build Kc + zero table + reset ticket ----------------
__global__ __launch_bounds__(256) void k_pre(const unsigned int* __restrict__ xw,
                                             const unsigned int* __restrict__ bw) {
    __shared__ int sx[256];
    int t = threadIdx.x;
    int i = blockIdx.x * 256 + t;                    // node id (PREB*256 == NN)

    // zero 2 table slots per thread (16384 threads x 2 = 32768 slots)
    g_tab[2 * i]     = 0ULL;
    g_tab[2 * i + 1] = 0ULL;
    if (i == 0) g_chunkCtr = 0;

    // x values < 16: odd words all-zero iff int64 (P[false pos] = 16^-512)
    int cx = (t < 512 && xw[2 * t + 1]) ? 1 : 0;
    sx[t] = cx;
    __syncthreads();
#pragma unroll
    for (int o = 128; o > 0; o >>= 1) { if (t < o) sx[t] += sx[t + o]; __syncthreads(); }
    int x64 = (sx[0] == 0) ? 1 : 0;

    if (blockIdx.x == 0) {
        int cb = (t < 512 && bw[2 * t + 1]) ? 1 : 0;
        sx[t] = cb;
        __syncthreads();
#pragma unroll
        for (int o = 128; o > 0; o >>= 1) { if (t < o) sx[t] += sx[t + o]; __syncthreads(); }
        if (t == 0) { g_b64 = (sx[0] == 0) ? 1 : 0; g_x64 = x64; }
    }

    int xv = load_small(xw, i, x64);
    g_Kc[i] = (unsigned int)(mix64(0x123456789ABCDEFULL +
                                   (unsigned long long)xv * 0x9E3779B97F4A7C15ULL) >> 16);
}

// ---------------- k_main: persistent heavy pass + insert + post phases ----------------
__global__ __launch_bounds__(256, 5) void k_main(const float* __restrict__ adj,
                                                 const unsigned int* __restrict__ xw,
                                                 const unsigned int* __restrict__ bw,
                                                 float* __restrict__ out,
                                                 long long out_size) {
    int t = threadIdx.x;
    int bid = blockIdx.x;
    int lane = t & 31, w = t >> 5;
    long long histElems = (long long)BB * NN;
    bool haveHist = (out_size >= histElems);

    // distributed zeroing of k_post-only scratch (race-free: written only after barrier 0)
    {
        int4* c4 = (int4*)g_counts;
        float4* o4 = (float4*)out;
        int4 z = make_int4(0, 0, 0, 0);
        float4 fz = make_float4(0.f, 0.f, 0.f, 0.f);
        for (int j = bid * 256 + t; j < BB * NN / 4; j += MAINB * 256) {
            c4[j] = z;
            if (haveHist) o4[j] = fz;
        }
        if (bid == 0 && t < 64) g_norm2[t] = 0;
    }

    // ---- heavy chunks, dynamic tickets (fine-grained balance) ----
    __shared__ int sChunk;
    const uint4* __restrict__ kt = (const uint4*)g_Kc;
    for (;;) {
        __syncthreads();
        if (t == 0) sChunk = atomicAdd(&g_chunkCtr, 1);
        __syncthreads();
        int chunk = sChunk;
        if (chunk >= K1B) break;

        int row = chunk * 8 + w;
        const uint4* __restrict__ arow = (const uint4*)(adj + (size_t)row * NN);
        unsigned long long a0 = 0, a1 = 0, a2 = 0, a3 = 0;
#pragma unroll 4
        for (int q = lane; q < 4096; q += 128) {
            uint4 u0 = __ldcs(arow + q);
            uint4 u1 = __ldcs(arow + q + 32);
            uint4 u2 = __ldcs(arow + q + 64);
            uint4 u3 = __ldcs(arow + q + 96);
            uint4 c0 = kt[q];
            uint4 c1 = kt[q + 32];
            uint4 c2 = kt[q + 64];
            uint4 c3 = kt[q + 96];
            a0 += (unsigned long long)u0.x * c0.x + (unsigned long long)u0.y * c0.y
                + (unsigned long long)u0.z * c0.z + (unsigned long long)u0.w * c0.w;
            a1 += (unsigned long long)u1.x * c1.x + (unsigned long long)u1.y * c1.y
                + (unsigned long long)u1.z * c1.z + (unsigned long long)u1.w * c1.w;
            a2 += (unsigned long long)u2.x * c2.x + (unsigned long long)u2.y * c2.y
                + (unsigned long long)u2.z * c2.z + (unsigned long long)u2.w * c2.w;
            a3 += (unsigned long long)u3.x * c3.x + (unsigned long long)u3.y * c3.y
                + (unsigned long long)u3.z * c3.z + (unsigned long long)u3.w * c3.w;
        }
        unsigned long long a = (a0 + a1) + (a2 + a3);
#pragma unroll
        for (int o = 16; o > 0; o >>= 1) a += __shfl_down_sync(0xffffffffu, a, o);

        // tail: lane 0 of each warp inserts its row into the hash table
        if (lane == 0) {
            unsigned long long acc = a;
            bool iso = false;
            if (acc == 0ULL) {                       // w.p. ~2^-41 for non-isolated: exact check
                bool any = false;
                const float* rp = adj + (size_t)row * NN;
                for (int j = 0; j < NN && !any; j++) if (rp[j] != 0.0f) any = true;
                for (int r = 0; r < NN && !any; r++) if (adj[(size_t)r * NN + row] != 0.0f) any = true;
                iso = !any;
            }
            unsigned long long hk = 0ULL;            // high-50-bit key, top bit set (never 0)
            if (!iso) {
                int xv = load_small(xw, row, g_x64);
                unsigned long long h = mix64(acc + (unsigned long long)xv * 0xA24BAED4963EE407ULL);
                hk = (h | 0x8000000000000000ULL) & 0xFFFFFFFFFFFFC000ULL;
                unsigned long long val = hk | (unsigned long long)row;
                unsigned int s = (unsigned int)(h >> 32) & (TS - 1);
                for (int p = 0; p < TS; p++) {       // bounded probe (defensive)
                    unsigned long long prev = atomicCAS(&g_tab[s], 0ULL, val);
                    if (prev == 0ULL) break;
                    if ((prev & 0xFFFFFFFFFFFFC000ULL) == hk) { atomicMin(&g_tab[s], val); break; }
                    s = (s + 1) & (TS - 1);
                }
            }
            g_key[row] = hk;
        }
    }

    gridBarrier(0, MAINB);                           // all inserts + zeroing complete
    if (bid >= POSTB) return;                        // blocks 64..739 done

    // ================= post phases (blocks 0..63, node i per thread) =================
    int i = bid * 256 + t;
    long long colorBase = haveHist ? histElems : 0;

    // ---- phase A: lookup first-occurrence + shuffle scan of is_first ----
    unsigned long long hk = g_key[i];
    int f = -1;
    if (hk) {
        unsigned int s = (unsigned int)(hk >> 32) & (TS - 1);  // hk>>32 == h>>32 (mask clears low 14 bits)
        for (int p = 0; p < TS; p++) {
            unsigned long long v = g_tab[s];
            if ((v & 0xFFFFFFFFFFFFC000ULL) == hk) { f = (int)(v & 0x3FFFULL); break; }
            s = (s + 1) & (TS - 1);
        }
    }
    int gb = load_small(bw, i, g_b64) & (BB - 1);    // prefetch batch id (used in phase B)

    int isf = (f == i) ? 1 : 0;
    int v = isf;
#pragma unroll
    for (int o = 1; o < 32; o <<= 1) {
        int n = __shfl_up_sync(0xffffffffu, v, o);
        if (lane >= o) v += n;
    }
    __shared__ int sW[8];
    if (lane == 31) sW[w] = v;
    __syncthreads();
    int woff = 0;
#pragma unroll
    for (int b = 0; b < 8; b++) woff += (b < w) ? sW[b] : 0;
    int incl = v + woff;                             // inclusive in-block prefix
    g_rank[i] = incl;
    if (t == 255) g_bsum[bid] = incl;
    gridBarrier(1, POSTB);

    // ---- phase B: parallel sOff scan + global rank + emit + incremental norm ----
    __shared__ int sBs[POSTB];
    __shared__ int sOff[POSTB];
    __shared__ int sW0tot;
    if (t < POSTB) sBs[t] = g_bsum[t];
    __syncthreads();
    int v2 = 0;
    if (t < POSTB) {
        v2 = sBs[t];
#pragma unroll
        for (int o = 1; o < 32; o <<= 1) {
            int n = __shfl_up_sync(0xffffffffu, v2, o);
            if (lane >= o) v2 += n;
        }
        if (t == 31) sW0tot = v2;
    }
    __syncthreads();
    if (t < POSTB) {
        int add = (t >= 32) ? sW0tot : 0;
        sOff[t] = v2 + add - sBs[t];                 // exclusive prefix of block sums
    }
    __syncthreads();
    int c = (f < 0) ? 0 : (g_rank[f] + sOff[f >> 8]);
    if (c > 0) {
        int old = atomicAdd(&g_counts[gb * NN + (c - 1)], 1);
        atomicAdd(&g_norm2[gb], 2 * old + 1);        // sum count^2, incrementally exact
    }
    long long oi = colorBase + i;
    if (oi < out_size) out[oi] = (float)c;
    gridBarrier(2, POSTB);                           // counts + norm2 final

    // ---- phase C: sparse normalize (scatter only touched cells) ----
    if (haveHist) {
        if (c > 0) {
            int cv = g_counts[gb * NN + (c - 1)];    // final count (coherent load)
            double norm = sqrt((double)g_norm2[gb]);
            out[(size_t)gb * NN + (c - 1)] = (float)((double)cv / norm);
        }
        // rare exactness path: all-zero graph row -> reference 0/0 = NaN everywhere
        if (g_norm2[bid] == 0) {
            float nanv = __int_as_float(0x7FC00000);
            float4 n4 = make_float4(nanv, nanv, nanv, nanv);
            float4* o4 = (float4*)(out + (size_t)bid * NN);
            for (int j = t; j < NN / 4; j += 256) o4[j] = n4;
        }
    }
}

// ---------------- launcher ----------------
extern "C" void kernel_launch(void* const* d_in, const int* in_sizes, int n_in,
                              void* d_out, int out_size) {
    int iA = -1;
    for (int i = 0; i < n_in; i++)
        if ((long long)in_sizes[i] == (long long)NN * (long long)NN) iA = i;
    if (iA < 0) iA = (n_in > 1) ? 1 : 0;
    int ix = -1, ib = -1;
    for (int i = 0; i < n_in; i++) {
        if (i == iA) continue;
        if (ix < 0) ix = i; else if (ib < 0) ib = i;
    }
    if (ix < 0) ix = 0;
    if (ib < 0) ib = ix;

    const unsigned int* xw  = (const unsigned int*)d_in[ix];
    const float*        adj = (const float*)d_in[iA];
    const unsigned int* bw  = (const unsigned int*)d_in[ib];
    float* out = (float*)d_out;
    long long osz = (long long)out_size;

    k_pre<<<PREB, 256>>>(xw, bw);                    // idx 0 (table zero + Kc + ticket reset)
    k_main<<<MAINB, 256>>>(adj, xw, bw, out, osz);   // idx 1 (persistent: heavy + post)
}